// round 7
// baseline (speedup 1.0000x reference)
#include <cuda_runtime.h>
#include <cuda_fp16.h>
#include <math.h>
#include <stdint.h>

#define NN 8192
#define FF 256
#define LRA 0.2f
#define KSPLIT 2
#define MB 128                  // i-rows per block in k_attn
#define KT 64                   // j (K-dim) per tile
#define JSPAN (NN / KSPLIT)     // 4096
#define NTILE (JSPAN / KT)      // 64

#define PSTRIDE 72                       // halves per P row (144 B)
#define PBUF_BYTES (128 * PSTRIDE * 2)   // 18432
#define BSTRIDE 264                      // halves per B row (528 B)
#define BBUF_BYTES (64 * BSTRIDE * 2)    // 33792

// ---------------- scratch (device globals: no allocs allowed) ----------------
__device__ __half g_Wh[NN * FF];            // 4 MB, fp16 Wh[j][f]
__device__ float g_s1[NN];
__device__ float g_s2[NN];
__device__ float g_E1[NN];
__device__ float g_E2[NN];
__device__ float g_F1[NN];
__device__ float g_F2[NN];
__device__ float g_maxS2;
__device__ float g_Opart[KSPLIT * NN * FF]; // 16 MB partial numerators
__device__ float g_den[KSPLIT * NN];        // partial denominators

// ---------------- packed f32x2 helpers (for K1) ------------------------------
__device__ __forceinline__ unsigned long long pk_dup(float x) {
    unsigned long long r;
    asm("mov.b64 %0, {%1, %1};" : "=l"(r) : "f"(x));
    return r;
}
__device__ __forceinline__ void ffma2(unsigned long long &d,
                                      unsigned long long a,
                                      unsigned long long b) {
    asm("fma.rn.f32x2 %0, %1, %2, %0;" : "+l"(d) : "l"(a), "l"(b));
}

// ---------------- mma / ldmatrix / cp.async helpers --------------------------
__device__ __forceinline__ uint32_t smem_u32(const void* p) {
    uint32_t a;
    asm("{ .reg .u64 t; cvta.to.shared.u64 t, %1; cvt.u32.u64 %0, t; }"
        : "=r"(a) : "l"(p));
    return a;
}
__device__ __forceinline__ void cp16(uint32_t dst, const void* src) {
    asm volatile("cp.async.cg.shared.global [%0], [%1], 16;"
                 :: "r"(dst), "l"(src) : "memory");
}
#define LDM4(d, addr)                                                          \
    asm volatile("ldmatrix.sync.aligned.m8n8.x4.shared.b16 {%0,%1,%2,%3}, [%4];" \
        : "=r"((d)[0]), "=r"((d)[1]), "=r"((d)[2]), "=r"((d)[3]) : "r"(addr))
#define LDM4T(d0, d1, d2, d3, addr)                                            \
    asm volatile("ldmatrix.sync.aligned.m8n8.x4.trans.shared.b16 {%0,%1,%2,%3}, [%4];" \
        : "=r"(d0), "=r"(d1), "=r"(d2), "=r"(d3) : "r"(addr))

__device__ __forceinline__ void mma16816(float* c, const uint32_t* a,
                                         uint32_t b0, uint32_t b1) {
    asm volatile(
        "mma.sync.aligned.m16n8k16.row.col.f32.f16.f16.f32 "
        "{%0,%1,%2,%3}, {%4,%5,%6,%7}, {%8,%9}, {%0,%1,%2,%3};"
        : "+f"(c[0]), "+f"(c[1]), "+f"(c[2]), "+f"(c[3])
        : "r"(a[0]), "r"(a[1]), "r"(a[2]), "r"(a[3]), "r"(b0), "r"(b1));
}

// ==================== K1: Wh = h @ W (fp16 out), fused s1/s2 =================
__global__ void __launch_bounds__(256, 1)
k_wh(const float* __restrict__ h, const float* __restrict__ W,
     const float* __restrict__ a) {
    __shared__ float As[64 * 32];
    __shared__ float Ws[32 * 256];
    const int tid = threadIdx.x;
    const int i0 = blockIdx.x * 64;
    const int ty = tid >> 5, tx = tid & 31;
    const int r0 = ty * 8, c0 = tx * 8;

    unsigned long long acc[8][4];
#pragma unroll
    for (int r = 0; r < 8; r++)
#pragma unroll
        for (int p = 0; p < 4; p++) acc[r][p] = 0ull;

    for (int ko = 0; ko < FF; ko += 32) {
        __syncthreads();
#pragma unroll
        for (int t = 0; t < 2; t++) {
            int idx = t * 256 + tid;
            int row = idx >> 3, c4 = idx & 7;
            float4 v = *(const float4*)&h[(size_t)(i0 + row) * FF + ko + c4 * 4];
            *(float4*)&As[row * 32 + c4 * 4] = v;
        }
#pragma unroll
        for (int t = 0; t < 8; t++) {
            int idx = t * 256 + tid;
            int row = idx >> 6, c4 = idx & 63;
            float4 v = *(const float4*)&W[(size_t)(ko + row) * FF + c4 * 4];
            *(float4*)&Ws[row * 256 + c4 * 4] = v;
        }
        __syncthreads();
        for (int kk = 0; kk < 32; kk += 4) {
            float4 pv[8];
#pragma unroll
            for (int r = 0; r < 8; r++)
                pv[r] = *(const float4*)&As[(r0 + r) * 32 + kk];
#pragma unroll
            for (int k4 = 0; k4 < 4; k4++) {
                ulonglong2 wa = *(const ulonglong2*)&Ws[(kk + k4) * 256 + c0];
                ulonglong2 wb = *(const ulonglong2*)&Ws[(kk + k4) * 256 + c0 + 4];
#pragma unroll
                for (int r = 0; r < 8; r++) {
                    float p = (k4 == 0) ? pv[r].x : (k4 == 1) ? pv[r].y
                             : (k4 == 2) ? pv[r].z : pv[r].w;
                    unsigned long long pd = pk_dup(p);
                    ffma2(acc[r][0], pd, wa.x);
                    ffma2(acc[r][1], pd, wa.y);
                    ffma2(acc[r][2], pd, wb.x);
                    ffma2(acc[r][3], pd, wb.y);
                }
            }
        }
    }
    float mat[8][8];
#pragma unroll
    for (int r = 0; r < 8; r++)
#pragma unroll
        for (int p = 0; p < 4; p++) {
            float2 f = *(float2*)&acc[r][p];
            mat[r][2 * p] = f.x; mat[r][2 * p + 1] = f.y;
        }
    float a1c[8], a2c[8];
#pragma unroll
    for (int c = 0; c < 8; c++) { a1c[c] = a[c0 + c]; a2c[c] = a[FF + c0 + c]; }
#pragma unroll
    for (int r = 0; r < 8; r++) {
        float p1 = 0.f, p2 = 0.f;
#pragma unroll
        for (int c = 0; c < 8; c++) { p1 += mat[r][c] * a1c[c]; p2 += mat[r][c] * a2c[c]; }
#pragma unroll
        for (int off = 16; off > 0; off >>= 1) {
            p1 += __shfl_down_sync(0xffffffffu, p1, off);
            p2 += __shfl_down_sync(0xffffffffu, p2, off);
        }
        if (tx == 0) { g_s1[i0 + r0 + r] = p1; g_s2[i0 + r0 + r] = p2; }
    }
#pragma unroll
    for (int r = 0; r < 8; r++) {
        __half2 q0 = __floats2half2_rn(mat[r][0], mat[r][1]);
        __half2 q1 = __floats2half2_rn(mat[r][2], mat[r][3]);
        __half2 q2 = __floats2half2_rn(mat[r][4], mat[r][5]);
        __half2 q3 = __floats2half2_rn(mat[r][6], mat[r][7]);
        uint4 u = make_uint4(*(uint32_t*)&q0, *(uint32_t*)&q1,
                             *(uint32_t*)&q2, *(uint32_t*)&q3);
        *(uint4*)&g_Wh[(size_t)(i0 + r0 + r) * FF + c0] = u;
    }
}

// ==================== K2: maxS2 = max(s2) ====================================
__global__ void k_max() {
    __shared__ float sm[256];
    int tid = threadIdx.x;
    float v = -1e30f;
    for (int i = tid; i < NN; i += 256) v = fmaxf(v, g_s2[i]);
    sm[tid] = v;
    __syncthreads();
    for (int s = 128; s > 0; s >>= 1) {
        if (tid < s) sm[tid] = fmaxf(sm[tid], sm[tid + s]);
        __syncthreads();
    }
    if (tid == 0) g_maxS2 = sm[0];
}

// ==================== K3: factorized-exp precompute ==========================
__global__ void k_factors() {
    int i = blockIdx.x * blockDim.x + threadIdx.x;
    if (i >= NN) return;
    float s1 = g_s1[i], s2 = g_s2[i], m = g_maxS2;
    g_F1[i] = __expf(s2);
    g_F2[i] = __expf(LRA * s2);
    float x = s1 + m;
    float B = x > 0.f ? x : LRA * x;
    g_E1[i] = __expf(s1 - B);
    g_E2[i] = __expf(LRA * s1 - B);
}

// ==================== K4: fp16 mma.sync fused masked-softmax @ Wh ============
// grid (KSPLIT, 64), 512 thr (16 warps, warp tile 32x64), KT=64.
// P double-buffered, B triple-buffered (cp.async distance-2), adj regs dist-2.
__global__ void __launch_bounds__(512, 1)
k_attn(const int* __restrict__ adj) {
    extern __shared__ char smem[];
    const uint32_t PsB = smem_u32(smem);
    const uint32_t BsB = PsB + 2 * PBUF_BYTES;

    const int tid = threadIdx.x;
    const int lane = tid & 31, wid = tid >> 5;
    const int split = blockIdx.x;
    const int i0 = blockIdx.y * MB;
    const int jb = split * JSPAN;
    const int prow = tid >> 2;          // P row 0..127 (4 threads/row)
    const int jq16 = (tid & 3) * 16;    // 16 j's per thread
    const int wm = (wid & 3) * 32;      // warp M offset
    const int wn = (wid >> 2) * 64;     // warp N offset

    const float rs1 = g_s1[i0 + prow];
    const float rE1 = g_E1[i0 + prow];
    const float rE2 = g_E2[i0 + prow];
    float dloc = 0.f;

    const uint32_t Aoff = (uint32_t)(wm + (lane & 15)) * (PSTRIDE * 2) +
                          (uint32_t)(lane >> 4) * 16;
    const uint32_t Boff = (uint32_t)(lane & 15) * (BSTRIDE * 2) +
                          (uint32_t)(wn + (lane >> 4) * 8) * 2;
    const uint32_t Poff = (uint32_t)prow * (PSTRIDE * 2) + (uint32_t)jq16 * 2;

    float acc[2][8][4];
#pragma unroll
    for (int mf = 0; mf < 2; mf++)
#pragma unroll
        for (int nf = 0; nf < 8; nf++)
#pragma unroll
            for (int q = 0; q < 4; q++) acc[mf][nf][q] = 0.f;

    int4 avA[4], avB[4];    // adj prefetch register sets (parity-indexed)

    auto ldav = [&](int tt, int4* av) {
        const size_t base = (size_t)(i0 + prow) * NN + jb + tt * KT + jq16;
#pragma unroll
        for (int q = 0; q < 4; q++) av[q] = *(const int4*)&adj[base + 4 * q];
    };
    auto buildP = [&](int tt, uint32_t pb, const int4* av) {
        const int j0 = jb + tt * KT + jq16;
        float4 s2v[4], f1v[4], f2v[4];
#pragma unroll
        for (int q = 0; q < 4; q++) {   // all LDGs issue before any use
            s2v[q] = *(const float4*)&g_s2[j0 + 4 * q];
            f1v[q] = *(const float4*)&g_F1[j0 + 4 * q];
            f2v[q] = *(const float4*)&g_F2[j0 + 4 * q];
        }
        const float ms1 = -rs1;
        uint32_t hp[8];
#pragma unroll
        for (int q = 0; q < 4; q++) {
            float w0 = av[q].x > 0 ? (s2v[q].x >= ms1 ? rE1 * f1v[q].x : rE2 * f2v[q].x) : 0.f;
            float w1 = av[q].y > 0 ? (s2v[q].y >= ms1 ? rE1 * f1v[q].y : rE2 * f2v[q].y) : 0.f;
            float w2 = av[q].z > 0 ? (s2v[q].z >= ms1 ? rE1 * f1v[q].z : rE2 * f2v[q].z) : 0.f;
            float w3 = av[q].w > 0 ? (s2v[q].w >= ms1 ? rE1 * f1v[q].w : rE2 * f2v[q].w) : 0.f;
            __half2 h0 = __floats2half2_rn(w0, w1);
            __half2 h1 = __floats2half2_rn(w2, w3);
            float2 c0 = __half22float2(h0), c1 = __half22float2(h1);
            dloc += (c0.x + c0.y) + (c1.x + c1.y);
            hp[2 * q] = *(uint32_t*)&h0;
            hp[2 * q + 1] = *(uint32_t*)&h1;
        }
        asm volatile("st.shared.v4.b32 [%0], {%1,%2,%3,%4};"
                     :: "r"(pb + Poff), "r"(hp[0]), "r"(hp[1]), "r"(hp[2]), "r"(hp[3])
                     : "memory");
        asm volatile("st.shared.v4.b32 [%0], {%1,%2,%3,%4};"
                     :: "r"(pb + Poff + 16), "r"(hp[4]), "r"(hp[5]), "r"(hp[6]), "r"(hp[7])
                     : "memory");
    };
    auto cpB = [&](int tt, uint32_t bb) {
        const int j0 = jb + tt * KT;
#pragma unroll
        for (int k = 0; k < 4; k++) {
            int c = tid + k * 512;
            int jr = c >> 5, fo = (c & 31) * 8;
            cp16(bb + (uint32_t)jr * (BSTRIDE * 2) + (uint32_t)fo * 2,
                 &g_Wh[(size_t)(j0 + jr) * FF + fo]);
        }
    };
    auto mmaT = [&](uint32_t Pb, uint32_t Bb) {
#pragma unroll
        for (int kf = 0; kf < 4; kf++) {
            uint32_t afr0[4], afr1[4];
            LDM4(afr0, Pb + Aoff + kf * 32);
            LDM4(afr1, Pb + Aoff + 16 * (PSTRIDE * 2) + kf * 32);
#pragma unroll
            for (int nfp = 0; nfp < 4; nfp++) {
                uint32_t b0, b1, b2, b3;
                LDM4T(b0, b1, b2, b3,
                      Bb + Boff + nfp * 32 + kf * 16 * (BSTRIDE * 2));
                mma16816(acc[0][2 * nfp],     afr0, b0, b1);
                mma16816(acc[1][2 * nfp],     afr1, b0, b1);
                mma16816(acc[0][2 * nfp + 1], afr0, b2, b3);
                mma16816(acc[1][2 * nfp + 1], afr1, b2, b3);
            }
        }
    };

    // ---- prologue ----
    ldav(0, avA);
    cpB(0, BsB);
    asm volatile("cp.async.commit_group;" ::: "memory");
    ldav(1, avB);
    cpB(1, BsB + BBUF_BYTES);
    asm volatile("cp.async.commit_group;" ::: "memory");
    buildP(0, PsB, avA);
    asm volatile("cp.async.wait_group 1;" ::: "memory");
    __syncthreads();

    uint32_t bcur = 0, bnext2 = 2;   // B buffer indices (mod 3)
#pragma unroll 1
    for (int t = 0; t < NTILE; t += 2) {
        // ---- even tile: MMA(t) [P0, Bcur]; build P(t+1); prefetch t+2 ----
        mmaT(PsB, BsB + bcur * BBUF_BYTES);
        if (t + 2 < NTILE) {
            cpB(t + 2, BsB + bnext2 * BBUF_BYTES);
            ldav(t + 2, avA);
        }
        buildP(t + 1, PsB + PBUF_BYTES, avB);
        asm volatile("cp.async.commit_group;" ::: "memory");
        asm volatile("cp.async.wait_group 1;" ::: "memory");
        __syncthreads();
        bcur = (bcur == 2) ? 0 : bcur + 1;
        bnext2 = (bnext2 == 2) ? 0 : bnext2 + 1;

        // ---- odd tile: MMA(t+1) [P1, Bcur]; build P(t+2); prefetch t+3 ----
        mmaT(PsB + PBUF_BYTES, BsB + bcur * BBUF_BYTES);
        if (t + 3 < NTILE) {
            cpB(t + 3, BsB + bnext2 * BBUF_BYTES);
            ldav(t + 3, avB);
        }
        if (t + 2 < NTILE) buildP(t + 2, PsB, avA);
        asm volatile("cp.async.commit_group;" ::: "memory");
        asm volatile("cp.async.wait_group 1;" ::: "memory");
        __syncthreads();
        bcur = (bcur == 2) ? 0 : bcur + 1;
        bnext2 = (bnext2 == 2) ? 0 : bnext2 + 1;
    }

    // ---- denominators: 4 threads share each row ----
    dloc += __shfl_down_sync(0xffffffffu, dloc, 2, 4);
    dloc += __shfl_down_sync(0xffffffffu, dloc, 1, 4);
    if ((tid & 3) == 0) g_den[split * NN + i0 + prow] = dloc;

    // ---- partial O store ----
    float* Ob = g_Opart + (size_t)split * NN * FF;
    const int gid = lane >> 2, tig = lane & 3;
#pragma unroll
    for (int mf = 0; mf < 2; mf++)
#pragma unroll
        for (int nf = 0; nf < 8; nf++) {
            int r = i0 + wm + mf * 16 + gid;
            int c = wn + nf * 8 + 2 * tig;
            *(float2*)&Ob[(size_t)r * FF + c] =
                make_float2(acc[mf][nf][0], acc[mf][nf][1]);
            *(float2*)&Ob[(size_t)(r + 8) * FF + c] =
                make_float2(acc[mf][nf][2], acc[mf][nf][3]);
        }
}

// ==================== K5: combine splits, divide, elu ========================
__global__ void k_final(float* __restrict__ out) {
    int idx = blockIdx.x * blockDim.x + threadIdx.x;   // float4 index
    int i = idx >> 6;                                   // row
    float den = g_den[i] + g_den[NN + i];
    float inv = 1.0f / den;
    const float4* O = (const float4*)g_Opart;
    const int STR = NN * FF / 4;
    float4 a = O[idx], b = O[idx + STR];
    float4 r;
    r.x = (a.x + b.x) * inv;
    r.y = (a.y + b.y) * inv;
    r.z = (a.z + b.z) * inv;
    r.w = (a.w + b.w) * inv;
    r.x = r.x > 0.f ? r.x : expm1f(r.x);
    r.y = r.y > 0.f ? r.y : expm1f(r.y);
    r.z = r.z > 0.f ? r.z : expm1f(r.z);
    r.w = r.w > 0.f ? r.w : expm1f(r.w);
    ((float4*)out)[idx] = r;
}

// ==================== launch =================================================
extern "C" void kernel_launch(void* const* d_in, const int* in_sizes, int n_in,
                              void* d_out, int out_size) {
    const float* h   = (const float*)d_in[0];
    const int*   adj = (const int*)d_in[1];
    const float* W   = (const float*)d_in[2];
    const float* a   = (const float*)d_in[3];
    float* out = (float*)d_out;

    k_wh<<<NN / 64, 256>>>(h, W, a);
    k_max<<<1, 256>>>();
    k_factors<<<NN / 256, 256>>>();

    const int smem_attn = 2 * PBUF_BYTES + 3 * BBUF_BYTES;   // 138240
    cudaFuncSetAttribute(k_attn, cudaFuncAttributeMaxDynamicSharedMemorySize,
                         smem_attn);
    k_attn<<<dim3(KSPLIT, NN / MB), 512, smem_attn>>>(adj);

    k_final<<<(NN * FF / 4) / 256, 256>>>(out);
}

// round 8
// speedup vs baseline: 1.4246x; 1.4246x over previous
#include <cuda_runtime.h>
#include <cuda_fp16.h>
#include <math.h>
#include <stdint.h>

#define NN 8192
#define FF 256
#define LRA 0.2f
#define KSPLIT 2
#define MB 64                   // i-rows per block in k_attn
#define KT 32                   // j (K-dim) per tile
#define JSPAN (NN / KSPLIT)     // 4096
#define NTILE (JSPAN / KT)      // 128

#define PSTRIDE 40                       // halves per P row (80 B)
#define PBUF_BYTES (64 * PSTRIDE * 2)    // 5120
#define BSTRIDE 264                      // halves per B row (528 B)
#define BBUF_BYTES (32 * BSTRIDE * 2)    // 16896

// ---------------- scratch (device globals: no allocs allowed) ----------------
__device__ __half g_Wh[NN * FF];            // 4 MB, fp16 Wh[j][f]
__device__ float g_s1[NN];
__device__ float g_s2[NN];
__device__ float g_E1[NN];
__device__ float g_E2[NN];
__device__ float g_F1[NN];
__device__ float g_F2[NN];
__device__ float g_maxS2;
__device__ float g_Opart[KSPLIT * NN * FF]; // 16 MB partial numerators
__device__ float g_den[KSPLIT * NN];        // partial denominators

// ---------------- packed f32x2 helpers (for K1) ------------------------------
__device__ __forceinline__ unsigned long long pk_dup(float x) {
    unsigned long long r;
    asm("mov.b64 %0, {%1, %1};" : "=l"(r) : "f"(x));
    return r;
}
__device__ __forceinline__ void ffma2(unsigned long long &d,
                                      unsigned long long a,
                                      unsigned long long b) {
    asm("fma.rn.f32x2 %0, %1, %2, %0;" : "+l"(d) : "l"(a), "l"(b));
}

// ---------------- mma / ldmatrix / cp.async helpers --------------------------
__device__ __forceinline__ uint32_t smem_u32(const void* p) {
    uint32_t a;
    asm("{ .reg .u64 t; cvta.to.shared.u64 t, %1; cvt.u32.u64 %0, t; }"
        : "=r"(a) : "l"(p));
    return a;
}
__device__ __forceinline__ void cp16(uint32_t dst, const void* src) {
    asm volatile("cp.async.cg.shared.global [%0], [%1], 16;"
                 :: "r"(dst), "l"(src) : "memory");
}
#define LDM4(d, addr)                                                          \
    asm volatile("ldmatrix.sync.aligned.m8n8.x4.shared.b16 {%0,%1,%2,%3}, [%4];" \
        : "=r"((d)[0]), "=r"((d)[1]), "=r"((d)[2]), "=r"((d)[3]) : "r"(addr))
#define LDM4T(d0, d1, d2, d3, addr)                                            \
    asm volatile("ldmatrix.sync.aligned.m8n8.x4.trans.shared.b16 {%0,%1,%2,%3}, [%4];" \
        : "=r"(d0), "=r"(d1), "=r"(d2), "=r"(d3) : "r"(addr))

__device__ __forceinline__ void mma16816(float* c, const uint32_t* a,
                                         uint32_t b0, uint32_t b1) {
    asm volatile(
        "mma.sync.aligned.m16n8k16.row.col.f32.f16.f16.f32 "
        "{%0,%1,%2,%3}, {%4,%5,%6,%7}, {%8,%9}, {%0,%1,%2,%3};"
        : "+f"(c[0]), "+f"(c[1]), "+f"(c[2]), "+f"(c[3])
        : "r"(a[0]), "r"(a[1]), "r"(a[2]), "r"(a[3]), "r"(b0), "r"(b1));
}

// ==================== K1: Wh = h @ W (fp16 out), fused s1/s2 =================
__global__ void __launch_bounds__(256, 1)
k_wh(const float* __restrict__ h, const float* __restrict__ W,
     const float* __restrict__ a) {
    __shared__ float As[64 * 32];
    __shared__ float Ws[32 * 256];
    const int tid = threadIdx.x;
    const int i0 = blockIdx.x * 64;
    const int ty = tid >> 5, tx = tid & 31;
    const int r0 = ty * 8, c0 = tx * 8;

    unsigned long long acc[8][4];
#pragma unroll
    for (int r = 0; r < 8; r++)
#pragma unroll
        for (int p = 0; p < 4; p++) acc[r][p] = 0ull;

    for (int ko = 0; ko < FF; ko += 32) {
        __syncthreads();
#pragma unroll
        for (int t = 0; t < 2; t++) {
            int idx = t * 256 + tid;
            int row = idx >> 3, c4 = idx & 7;
            float4 v = *(const float4*)&h[(size_t)(i0 + row) * FF + ko + c4 * 4];
            *(float4*)&As[row * 32 + c4 * 4] = v;
        }
#pragma unroll
        for (int t = 0; t < 8; t++) {
            int idx = t * 256 + tid;
            int row = idx >> 6, c4 = idx & 63;
            float4 v = *(const float4*)&W[(size_t)(ko + row) * FF + c4 * 4];
            *(float4*)&Ws[row * 256 + c4 * 4] = v;
        }
        __syncthreads();
        for (int kk = 0; kk < 32; kk += 4) {
            float4 pv[8];
#pragma unroll
            for (int r = 0; r < 8; r++)
                pv[r] = *(const float4*)&As[(r0 + r) * 32 + kk];
#pragma unroll
            for (int k4 = 0; k4 < 4; k4++) {
                ulonglong2 wa = *(const ulonglong2*)&Ws[(kk + k4) * 256 + c0];
                ulonglong2 wb = *(const ulonglong2*)&Ws[(kk + k4) * 256 + c0 + 4];
#pragma unroll
                for (int r = 0; r < 8; r++) {
                    float p = (k4 == 0) ? pv[r].x : (k4 == 1) ? pv[r].y
                             : (k4 == 2) ? pv[r].z : pv[r].w;
                    unsigned long long pd = pk_dup(p);
                    ffma2(acc[r][0], pd, wa.x);
                    ffma2(acc[r][1], pd, wa.y);
                    ffma2(acc[r][2], pd, wb.x);
                    ffma2(acc[r][3], pd, wb.y);
                }
            }
        }
    }
    float mat[8][8];
#pragma unroll
    for (int r = 0; r < 8; r++)
#pragma unroll
        for (int p = 0; p < 4; p++) {
            float2 f = *(float2*)&acc[r][p];
            mat[r][2 * p] = f.x; mat[r][2 * p + 1] = f.y;
        }
    float a1c[8], a2c[8];
#pragma unroll
    for (int c = 0; c < 8; c++) { a1c[c] = a[c0 + c]; a2c[c] = a[FF + c0 + c]; }
#pragma unroll
    for (int r = 0; r < 8; r++) {
        float p1 = 0.f, p2 = 0.f;
#pragma unroll
        for (int c = 0; c < 8; c++) { p1 += mat[r][c] * a1c[c]; p2 += mat[r][c] * a2c[c]; }
#pragma unroll
        for (int off = 16; off > 0; off >>= 1) {
            p1 += __shfl_down_sync(0xffffffffu, p1, off);
            p2 += __shfl_down_sync(0xffffffffu, p2, off);
        }
        if (tx == 0) { g_s1[i0 + r0 + r] = p1; g_s2[i0 + r0 + r] = p2; }
    }
#pragma unroll
    for (int r = 0; r < 8; r++) {
        __half2 q0 = __floats2half2_rn(mat[r][0], mat[r][1]);
        __half2 q1 = __floats2half2_rn(mat[r][2], mat[r][3]);
        __half2 q2 = __floats2half2_rn(mat[r][4], mat[r][5]);
        __half2 q3 = __floats2half2_rn(mat[r][6], mat[r][7]);
        uint4 u = make_uint4(*(uint32_t*)&q0, *(uint32_t*)&q1,
                             *(uint32_t*)&q2, *(uint32_t*)&q3);
        *(uint4*)&g_Wh[(size_t)(i0 + r0 + r) * FF + c0] = u;
    }
}

// ==================== K2: maxS2 = max(s2) ====================================
__global__ void k_max() {
    __shared__ float sm[256];
    int tid = threadIdx.x;
    float v = -1e30f;
    for (int i = tid; i < NN; i += 256) v = fmaxf(v, g_s2[i]);
    sm[tid] = v;
    __syncthreads();
    for (int s = 128; s > 0; s >>= 1) {
        if (tid < s) sm[tid] = fmaxf(sm[tid], sm[tid + s]);
        __syncthreads();
    }
    if (tid == 0) g_maxS2 = sm[0];
}

// ==================== K3: factorized-exp precompute ==========================
__global__ void k_factors() {
    int i = blockIdx.x * blockDim.x + threadIdx.x;
    if (i >= NN) return;
    float s1 = g_s1[i], s2 = g_s2[i], m = g_maxS2;
    g_F1[i] = __expf(s2);
    g_F2[i] = __expf(LRA * s2);
    float x = s1 + m;
    float B = x > 0.f ? x : LRA * x;
    g_E1[i] = __expf(s1 - B);
    g_E2[i] = __expf(LRA * s1 - B);
}

// ==================== K4: fp16 mma.sync fused masked-softmax @ Wh ============
// grid (KSPLIT, 128), 256 thr (8 warps, warp tile 32x64), 2 CTAs/SM.
// P triple-buffered, B quad-buffered (cp.async distance-2), 1 sync per tile.
__global__ void __launch_bounds__(256, 2)
k_attn(const int* __restrict__ adj) {
    extern __shared__ char smem[];
    const uint32_t PsB = smem_u32(smem);
    const uint32_t BsB = PsB + 3 * PBUF_BYTES;

    const int tid = threadIdx.x;
    const int lane = tid & 31, wid = tid >> 5;
    const int split = blockIdx.x;
    const int i0 = blockIdx.y * MB;
    const int jb = split * JSPAN;
    const int prow = tid >> 2;          // 0..63: this thread's P row
    const int jq = (tid & 3) * 8;       // 8 j's within tile
    const int wm = (wid & 1) * 32;      // warp M offset
    const int wn = (wid >> 1) * 64;     // warp N offset

    const float rs1 = g_s1[i0 + prow];
    const float rE1 = g_E1[i0 + prow];
    const float rE2 = g_E2[i0 + prow];
    float dloc = 0.f;

    const uint32_t Aoff = (uint32_t)(wm + (lane & 15)) * (PSTRIDE * 2) +
                          (uint32_t)(lane >> 4) * 16;
    const uint32_t Boff = (uint32_t)(lane & 15) * (BSTRIDE * 2) +
                          (uint32_t)(wn + (lane >> 4) * 8) * 2;
    const uint32_t Poff = (uint32_t)prow * (PSTRIDE * 2) + (uint32_t)jq * 2;

    float acc[2][8][4];
#pragma unroll
    for (int mf = 0; mf < 2; mf++)
#pragma unroll
        for (int nf = 0; nf < 8; nf++)
#pragma unroll
            for (int q = 0; q < 4; q++) acc[mf][nf][q] = 0.f;

    int4 av0, av1;

    auto ldav = [&](int tt) {
        const size_t base = (size_t)(i0 + prow) * NN + jb + tt * KT + jq;
        av0 = *(const int4*)&adj[base];
        av1 = *(const int4*)&adj[base + 4];
    };
    auto buildP = [&](int tt, uint32_t pb) {
        const int j0 = jb + tt * KT + jq;
        float4 f1a = *(const float4*)&g_F1[j0];
        float4 f2a = *(const float4*)&g_F2[j0];
        float4 s2a = *(const float4*)&g_s2[j0];
        float4 f1b = *(const float4*)&g_F1[j0 + 4];
        float4 f2b = *(const float4*)&g_F2[j0 + 4];
        float4 s2b = *(const float4*)&g_s2[j0 + 4];
        const float ms1 = -rs1;
        float w0 = av0.x > 0 ? (s2a.x >= ms1 ? rE1 * f1a.x : rE2 * f2a.x) : 0.f;
        float w1 = av0.y > 0 ? (s2a.y >= ms1 ? rE1 * f1a.y : rE2 * f2a.y) : 0.f;
        float w2 = av0.z > 0 ? (s2a.z >= ms1 ? rE1 * f1a.z : rE2 * f2a.z) : 0.f;
        float w3 = av0.w > 0 ? (s2a.w >= ms1 ? rE1 * f1a.w : rE2 * f2a.w) : 0.f;
        float w4 = av1.x > 0 ? (s2b.x >= ms1 ? rE1 * f1b.x : rE2 * f2b.x) : 0.f;
        float w5 = av1.y > 0 ? (s2b.y >= ms1 ? rE1 * f1b.y : rE2 * f2b.y) : 0.f;
        float w6 = av1.z > 0 ? (s2b.z >= ms1 ? rE1 * f1b.z : rE2 * f2b.z) : 0.f;
        float w7 = av1.w > 0 ? (s2b.w >= ms1 ? rE1 * f1b.w : rE2 * f2b.w) : 0.f;
        __half2 h0 = __floats2half2_rn(w0, w1);
        __half2 h1 = __floats2half2_rn(w2, w3);
        __half2 h2 = __floats2half2_rn(w4, w5);
        __half2 h3 = __floats2half2_rn(w6, w7);
        float2 c0 = __half22float2(h0), c1 = __half22float2(h1);
        float2 c2 = __half22float2(h2), c3 = __half22float2(h3);
        dloc += ((c0.x + c0.y) + (c1.x + c1.y)) + ((c2.x + c2.y) + (c3.x + c3.y));
        asm volatile("st.shared.v4.b32 [%0], {%1,%2,%3,%4};"
                     :: "r"(pb + Poff), "r"(*(uint32_t*)&h0), "r"(*(uint32_t*)&h1),
                        "r"(*(uint32_t*)&h2), "r"(*(uint32_t*)&h3) : "memory");
    };
    auto cpB = [&](int tt, uint32_t bb) {
        const int j0 = jb + tt * KT;
#pragma unroll
        for (int k = 0; k < 4; k++) {
            int c = tid + k * 256;
            int jr = c >> 5, fo = (c & 31) * 8;
            cp16(bb + (uint32_t)jr * (BSTRIDE * 2) + (uint32_t)fo * 2,
                 &g_Wh[(size_t)(j0 + jr) * FF + fo]);
        }
    };

    // ---- prologue ----
    ldav(0); buildP(0, PsB);
    cpB(0, BsB);
    asm volatile("cp.async.commit_group;" ::: "memory");
    ldav(1); buildP(1, PsB + PBUF_BYTES);
    cpB(1, BsB + BBUF_BYTES);
    asm volatile("cp.async.commit_group;" ::: "memory");
    ldav(2);
    cpB(2, BsB + 2 * BBUF_BYTES);
    asm volatile("cp.async.commit_group;" ::: "memory");
    asm volatile("cp.async.wait_group 2;" ::: "memory");
    __syncthreads();

    int p3 = 0, b4 = 0, p3n = 2, b4n = 3;
#pragma unroll 1
    for (int t = 0; t < NTILE; t++) {
        // ---- MMA(t) ----
        const uint32_t Pb = PsB + (uint32_t)p3 * PBUF_BYTES;
        const uint32_t Bb = BsB + (uint32_t)b4 * BBUF_BYTES;
#pragma unroll
        for (int kf = 0; kf < 2; kf++) {
            uint32_t afr0[4], afr1[4];
            LDM4(afr0, Pb + Aoff + kf * 32);
            LDM4(afr1, Pb + Aoff + 16 * (PSTRIDE * 2) + kf * 32);
#pragma unroll
            for (int nfp = 0; nfp < 4; nfp++) {
                uint32_t b0, b1, b2, b3;
                LDM4T(b0, b1, b2, b3, Bb + Boff + nfp * 32 + kf * 16 * (BSTRIDE * 2));
                mma16816(acc[0][2 * nfp],     afr0, b0, b1);
                mma16816(acc[1][2 * nfp],     afr1, b0, b1);
                mma16816(acc[0][2 * nfp + 1], afr0, b2, b3);
                mma16816(acc[1][2 * nfp + 1], afr1, b2, b3);
            }
        }
        // ---- overlapped producer work for future tiles ----
        if (t + 2 < NTILE) buildP(t + 2, PsB + (uint32_t)p3n * PBUF_BYTES);
        if (t + 3 < NTILE) {
            cpB(t + 3, BsB + (uint32_t)b4n * BBUF_BYTES);
            ldav(t + 3);
        }
        asm volatile("cp.async.commit_group;" ::: "memory");
        asm volatile("cp.async.wait_group 2;" ::: "memory");
        __syncthreads();
        p3 = (p3 + 1 == 3) ? 0 : p3 + 1;
        p3n = (p3n + 1 == 3) ? 0 : p3n + 1;
        b4 = (b4 + 1) & 3;
        b4n = (b4n + 1) & 3;
    }

    // ---- denominators: 4 threads share each row ----
    dloc += __shfl_down_sync(0xffffffffu, dloc, 2, 4);
    dloc += __shfl_down_sync(0xffffffffu, dloc, 1, 4);
    if ((tid & 3) == 0) g_den[split * NN + i0 + prow] = dloc;

    // ---- partial O store ----
    float* Ob = g_Opart + (size_t)split * NN * FF;
    const int gid = lane >> 2, tig = lane & 3;
#pragma unroll
    for (int mf = 0; mf < 2; mf++)
#pragma unroll
        for (int nf = 0; nf < 8; nf++) {
            int r = i0 + wm + mf * 16 + gid;
            int c = wn + nf * 8 + 2 * tig;
            *(float2*)&Ob[(size_t)r * FF + c] =
                make_float2(acc[mf][nf][0], acc[mf][nf][1]);
            *(float2*)&Ob[(size_t)(r + 8) * FF + c] =
                make_float2(acc[mf][nf][2], acc[mf][nf][3]);
        }
}

// ==================== K5: combine splits, divide, elu ========================
__global__ void k_final(float* __restrict__ out) {
    int idx = blockIdx.x * blockDim.x + threadIdx.x;   // float4 index
    int i = idx >> 6;                                   // row
    float den = g_den[i] + g_den[NN + i];
    float inv = 1.0f / den;
    const float4* O = (const float4*)g_Opart;
    const int STR = NN * FF / 4;
    float4 a = O[idx], b = O[idx + STR];
    float4 r;
    r.x = (a.x + b.x) * inv;
    r.y = (a.y + b.y) * inv;
    r.z = (a.z + b.z) * inv;
    r.w = (a.w + b.w) * inv;
    r.x = r.x > 0.f ? r.x : expm1f(r.x);
    r.y = r.y > 0.f ? r.y : expm1f(r.y);
    r.z = r.z > 0.f ? r.z : expm1f(r.z);
    r.w = r.w > 0.f ? r.w : expm1f(r.w);
    ((float4*)out)[idx] = r;
}

// ==================== launch =================================================
extern "C" void kernel_launch(void* const* d_in, const int* in_sizes, int n_in,
                              void* d_out, int out_size) {
    const float* h   = (const float*)d_in[0];
    const int*   adj = (const int*)d_in[1];
    const float* W   = (const float*)d_in[2];
    const float* a   = (const float*)d_in[3];
    float* out = (float*)d_out;

    k_wh<<<NN / 64, 256>>>(h, W, a);
    k_max<<<1, 256>>>();
    k_factors<<<NN / 256, 256>>>();

    const int smem_attn = 3 * PBUF_BYTES + 4 * BBUF_BYTES;   // 82944
    cudaFuncSetAttribute(k_attn, cudaFuncAttributeMaxDynamicSharedMemorySize,
                         smem_attn);
    k_attn<<<dim3(KSPLIT, NN / MB), 256, smem_attn>>>(adj);

    k_final<<<(NN * FF / 4) / 256, 256>>>(out);
}